// round 13
// baseline (speedup 1.0000x reference)
#include <cuda_runtime.h>
#include <cuda_bf16.h>

typedef unsigned int u32;

#define B_DIM 16
#define C_DIM 64
#define K_DIM 207
#define KL 13248            /* 207*64 */
#define KK 42849            /* 207*207 */
#define KP 256              /* padded k */
#define KLP 16384           /* KP*64 padded plane */

// bf16 hi/lo scratch (allocation-free rule: __device__ globals)
__device__ __nv_bfloat16 g_xh[(size_t)B_DIM*C_DIM*KLP];
__device__ __nv_bfloat16 g_xl[(size_t)B_DIM*C_DIM*KLP];
__device__ __nv_bfloat16 g_th[(size_t)4*B_DIM*C_DIM*KLP];
__device__ __nv_bfloat16 g_tl[(size_t)4*B_DIM*C_DIM*KLP];
__device__ __nv_bfloat16 g_ah[(size_t)2*B_DIM*KP*KP];
__device__ __nv_bfloat16 g_al[(size_t)2*B_DIM*KP*KP];
__device__ __nv_bfloat16 g_wh[64*320];
__device__ __nv_bfloat16 g_wl[64*320];

// ---------------------------------------------------------------- helpers
__device__ __forceinline__ u32 smem_u32(const void* p) {
    u32 a;
    asm("{ .reg .u64 t; cvta.to.shared.u64 t, %1; cvt.u32.u64 %0, t; }" : "=r"(a) : "l"(p));
    return a;
}
// pack {lo: v0, hi: v1} as bf16x2
__device__ __forceinline__ u32 cvt2bf(float v0, float v1) {
    u32 r; asm("cvt.rn.bf16x2.f32 %0, %1, %2;" : "=r"(r) : "f"(v1), "f"(v0)); return r;
}
__device__ __forceinline__ float bflo_f(u32 h){ return __uint_as_float(h << 16); }
__device__ __forceinline__ float bfhi_f(u32 h){ return __uint_as_float(h & 0xFFFF0000u); }

__device__ __forceinline__ void ldsm4(u32& r0,u32& r1,u32& r2,u32& r3, u32 a){
    asm volatile("ldmatrix.sync.aligned.m8n8.x4.shared.b16 {%0,%1,%2,%3}, [%4];"
        : "=r"(r0),"=r"(r1),"=r"(r2),"=r"(r3) : "r"(a) : "memory");
}
__device__ __forceinline__ void ldsm4t(u32& r0,u32& r1,u32& r2,u32& r3, u32 a){
    asm volatile("ldmatrix.sync.aligned.m8n8.x4.trans.shared.b16 {%0,%1,%2,%3}, [%4];"
        : "=r"(r0),"=r"(r1),"=r"(r2),"=r"(r3) : "r"(a) : "memory");
}
__device__ __forceinline__ void mma_bf(float* c, const u32* a, const u32* b){
    asm("mma.sync.aligned.m16n8k16.row.col.f32.bf16.bf16.f32 "
        "{%0,%1,%2,%3}, {%4,%5,%6,%7}, {%8,%9}, {%0,%1,%2,%3};"
        : "+f"(c[0]),"+f"(c[1]),"+f"(c[2]),"+f"(c[3])
        : "r"(a[0]),"r"(a[1]),"r"(a[2]),"r"(a[3]), "r"(b[0]),"r"(b[1]));
}
// XOR swizzles for row strides 128/256/512 B (XOR bits[6:4] by row bits[2:0])
__device__ __forceinline__ u32 swz128(u32 o){ return o ^ ((o >> 3) & 0x70); }
__device__ __forceinline__ u32 swz256(u32 o){ return o ^ ((o >> 4) & 0x70); }
__device__ __forceinline__ u32 swz512(u32 o){ return o ^ ((o >> 5) & 0x70); }

__device__ __forceinline__ void cpa16(u32 s, const void* g){
    asm volatile("cp.async.cg.shared.global [%0], [%1], 16;" :: "r"(s), "l"(g));
}
#define CP_COMMIT() asm volatile("cp.async.commit_group;" ::: "memory")
#define CP_WAIT(n)  asm volatile("cp.async.wait_group %0;" :: "n"(n) : "memory")

// ================= prep kernels: fp32 -> bf16 hi/lo, zero-padded ============
__global__ __launch_bounds__(256) void prep_x(const float* __restrict__ x) {
    size_t pe = ((size_t)blockIdx.x*256 + threadIdx.x) * 2;   // over B*C*KLP
    size_t plane = pe >> 14;
    int r = (int)(pe & 16383), k = r >> 6, l = r & 63;
    float v0 = 0.f, v1 = 0.f;
    if (k < K_DIM) {
        float2 v = *(const float2*)(x + plane*KL + (size_t)k*64 + l);
        v0 = v.x; v1 = v.y;
    }
    u32 h = cvt2bf(v0, v1);
    u32 lo = cvt2bf(v0 - bflo_f(h), v1 - bfhi_f(h));
    *(u32*)(g_xh + pe) = h;
    *(u32*)(g_xl + pe) = lo;
}
__global__ __launch_bounds__(256) void prep_a(
    const float* __restrict__ a0, const float* __restrict__ a1) {
    size_t pe = ((size_t)blockIdx.x*256 + threadIdx.x) * 2;   // over 2*B*KP*KP
    int sb = (int)(pe >> 16);
    int r = (int)(pe & 65535), j = r >> 8, k = r & 255;
    int s = sb >> 4, b = sb & 15;
    const float* A = (s ? a1 : a0) + (size_t)b*KK + (size_t)j*K_DIM;
    float v0 = (j < K_DIM && k     < K_DIM) ? A[k]     : 0.f;
    float v1 = (j < K_DIM && k + 1 < K_DIM) ? A[k + 1] : 0.f;
    u32 h = cvt2bf(v0, v1);
    u32 lo = cvt2bf(v0 - bflo_f(h), v1 - bfhi_f(h));
    *(u32*)(g_ah + pe) = h;
    *(u32*)(g_al + pe) = lo;
}
__global__ __launch_bounds__(256) void prep_w(const float* __restrict__ W) {
    size_t pe = ((size_t)blockIdx.x*256 + threadIdx.x) * 2;   // over 64*320
    float2 v = *(const float2*)(W + pe);
    u32 h = cvt2bf(v.x, v.y);
    u32 lo = cvt2bf(v.x - bflo_f(h), v.y - bfhi_f(h));
    *(u32*)(g_wh + pe) = h;
    *(u32*)(g_wl + pe) = lo;
}

// ================= diffuse: t[m][b][c][j][l] = sum_k M[j,k] src[c][k][l] ====
// pass0: src = x_bf (dst m = 2s); pass1: src = t_bf[m=2s] (dst m = 2s+1).
// CTA: 128 j x 256 n (4 ch x 64 l), 8 warps 64x64. K: 4 chunks of 64, DB'd.
#define DB_AH 0
#define DB_AL 16384
#define DB_BH 32768
#define DB_BL 65536
#define DB_SZ 98304
#define D_SMEM (2*DB_SZ)

__global__ __launch_bounds__(256, 1) void diffuse_mma(int pass)
{
    extern __shared__ char smn[];
    const u32 sb = smem_u32(smn);
    const int tid = threadIdx.x, lane = tid & 31, wid = tid >> 5;
    const int ct = blockIdx.x & 15, jt = blockIdx.x >> 4;
    const int s = blockIdx.y, b = blockIdx.z;
    const int j0 = jt*128;
    const int jm0 = (wid >> 2)*64, n0 = (wid & 3)*64, warp_n = wid & 3;

    const __nv_bfloat16* AH = g_ah + (size_t)(s*B_DIM + b)*KP*KP;
    const __nv_bfloat16* ALo = g_al + (size_t)(s*B_DIM + b)*KP*KP;
    const size_t cb = pass
        ? ((size_t)((s*2)*B_DIM + b)*C_DIM + ct*4)*KLP
        : ((size_t)(b*C_DIM) + ct*4)*KLP;
    const __nv_bfloat16* BH = (pass ? g_th : g_xh) + cb;
    const __nv_bfloat16* BL = (pass ? g_tl : g_xl) + cb;

    auto stage = [&](int chunk, u32 sbuf){
        const int kc = chunk*64;
        #pragma unroll
        for (int it = 0; it < 4; ++it) {          // A: 128 rows x 128B, hi+lo
            int e = tid + it*256;
            int j = e >> 3, q = e & 7;
            size_t go = (size_t)(j0 + j)*KP + kc + q*8;
            u32 so = swz128((u32)(j*128 + q*16));
            cpa16(sbuf + DB_AH + so, AH + go);
            cpa16(sbuf + DB_AL + so, ALo + go);
        }
        #pragma unroll
        for (int it = 0; it < 8; ++it) {          // B: 64 rows x 512B, hi+lo
            int e = tid + it*256;
            int k = e >> 5, q = e & 31;
            int c = q >> 3, l8 = (q & 7)*8;
            size_t go = (size_t)c*KLP + (size_t)(kc + k)*64 + l8;
            u32 so = swz512((u32)(k*512 + q*16));
            cpa16(sbuf + DB_BH + so, BH + go);
            cpa16(sbuf + DB_BL + so, BL + go);
        }
    };

    float acc[4][8][4];
    #pragma unroll
    for (int i = 0; i < 4; ++i)
        #pragma unroll
        for (int j = 0; j < 8; ++j)
            #pragma unroll
            for (int q = 0; q < 4; ++q) acc[i][j][q] = 0.f;

    stage(0, sb); CP_COMMIT();
    #pragma unroll 1
    for (int c = 0; c < 4; ++c) {
        if (c < 3) { stage(c + 1, sb + ((c + 1) & 1)*DB_SZ); CP_COMMIT(); }
        if (c < 3) { CP_WAIT(1); } else { CP_WAIT(0); }
        __syncthreads();
        const u32 buf = sb + (c & 1)*DB_SZ;
        const int nk = (c == 3) ? 1 : 4;
        #pragma unroll 1
        for (int kst = 0; kst < nk; ++kst) {
            #pragma unroll
            for (int p = 0; p < 3; ++p) {
                const u32 aoff = (p == 2) ? DB_AL : DB_AH;
                const u32 boff = (p == 1) ? DB_BL : DB_BH;
                u32 afr[4][4];
                #pragma unroll
                for (int mi = 0; mi < 4; ++mi)
                    ldsm4(afr[mi][0], afr[mi][1], afr[mi][2], afr[mi][3],
                          buf + aoff + swz128((u32)((jm0 + mi*16 + (lane & 15))*128
                                              + kst*32 + (lane >> 4)*16)));
                u32 bfr[8][2];
                #pragma unroll
                for (int nj = 0; nj < 4; ++nj) {
                    u32 r0, r1, r2, r3;
                    ldsm4t(r0, r1, r2, r3,
                           buf + boff + swz512((u32)((kst*16 + (lane & 15))*512
                                               + (n0 + nj*16)*2 + (lane >> 4)*16)));
                    bfr[nj*2][0] = r0; bfr[nj*2][1] = r1;
                    bfr[nj*2+1][0] = r2; bfr[nj*2+1][1] = r3;
                }
                #pragma unroll
                for (int mi = 0; mi < 4; ++mi)
                    #pragma unroll
                    for (int nt = 0; nt < 8; ++nt)
                        mma_bf(acc[mi][nt], afr[mi], bfr[nt]);
            }
        }
        __syncthreads();
    }

    // epilogue: f32 acc -> bf16 hi/lo, unconditional (padded rows are zeros)
    const size_t tb = ((size_t)((s*2 + pass)*B_DIM + b)*C_DIM + ct*4 + warp_n)*KLP;
    #pragma unroll
    for (int mi = 0; mi < 4; ++mi) {
        int r0 = j0 + jm0 + mi*16 + (lane >> 2);
        #pragma unroll
        for (int nt = 0; nt < 8; ++nt) {
            int l = nt*8 + (lane & 3)*2;
            u32 h0 = cvt2bf(acc[mi][nt][0], acc[mi][nt][1]);
            u32 l0 = cvt2bf(acc[mi][nt][0] - bflo_f(h0), acc[mi][nt][1] - bfhi_f(h0));
            *(u32*)(g_th + tb + (size_t)r0*64 + l) = h0;
            *(u32*)(g_tl + tb + (size_t)r0*64 + l) = l0;
            u32 h1 = cvt2bf(acc[mi][nt][2], acc[mi][nt][3]);
            u32 l1 = cvt2bf(acc[mi][nt][2] - bflo_f(h1), acc[mi][nt][3] - bfhi_f(h1));
            *(u32*)(g_th + tb + (size_t)(r0 + 8)*64 + l) = h1;
            *(u32*)(g_tl + tb + (size_t)(r0 + 8)*64 + l) = l1;
        }
    }
}

// ================= conv: y[b][o][kl] = sum_i W[o,i] H[i][kl] + bias[o] ======
// H blocks of 64 i: [x_bf | t_bf m=0..3]. CTA: 128 kl x 64 o, warp 32x32. DB'd.
#define CB_AH 0
#define CB_AL 16384
#define CB_BH 32768
#define CB_BL 40960
#define CB_SZ 49152
#define C_SMEM (2*CB_SZ)

__global__ __launch_bounds__(256, 2) void conv_mma(
    const float* __restrict__ bias, float* __restrict__ y)
{
    extern __shared__ char smn[];
    __shared__ float biass[64];
    const u32 sb = smem_u32(smn);
    const int tid = threadIdx.x, lane = tid & 31, wid = tid >> 5;
    const int b = blockIdx.y;
    const int kl0 = blockIdx.x * 128;
    const int klrow0 = (wid >> 1)*32, o0 = (wid & 1)*32;

    if (tid < 64) biass[tid] = bias[tid];

    auto stage = [&](int ch, u32 sbuf){
        const __nv_bfloat16* AH = (ch == 0)
            ? g_xh + (size_t)b*C_DIM*KLP
            : g_th + (size_t)((ch - 1)*B_DIM + b)*C_DIM*KLP;
        const __nv_bfloat16* ALo = (ch == 0)
            ? g_xl + (size_t)b*C_DIM*KLP
            : g_tl + (size_t)((ch - 1)*B_DIM + b)*C_DIM*KLP;
        #pragma unroll
        for (int it = 0; it < 4; ++it) {          // A: 64 rows x 256B, hi+lo
            int e = tid + it*256;
            int i = e >> 4, q = e & 15;
            size_t go = (size_t)i*KLP + kl0 + q*8;
            u32 so = swz256((u32)(i*256 + q*16));
            cpa16(sbuf + CB_AH + so, AH + go);
            cpa16(sbuf + CB_AL + so, ALo + go);
        }
        #pragma unroll
        for (int it = 0; it < 2; ++it) {          // B (W): 64 rows x 128B, hi+lo
            int e = tid + it*256;
            int o = e >> 3, q = e & 7;
            size_t go = (size_t)o*320 + ch*64 + q*8;
            u32 so = swz128((u32)(o*128 + q*16));
            cpa16(sbuf + CB_BH + so, g_wh + go);
            cpa16(sbuf + CB_BL + so, g_wl + go);
        }
    };

    float acc[2][4][4];
    #pragma unroll
    for (int i = 0; i < 2; ++i)
        #pragma unroll
        for (int j = 0; j < 4; ++j)
            #pragma unroll
            for (int q = 0; q < 4; ++q) acc[i][j][q] = 0.f;

    stage(0, sb); CP_COMMIT();
    #pragma unroll 1
    for (int c = 0; c < 5; ++c) {
        if (c < 4) { stage(c + 1, sb + ((c + 1) & 1)*CB_SZ); CP_COMMIT(); }
        if (c < 4) { CP_WAIT(1); } else { CP_WAIT(0); }
        __syncthreads();
        const u32 buf = sb + (c & 1)*CB_SZ;
        #pragma unroll 1
        for (int kst = 0; kst < 4; ++kst) {
            #pragma unroll
            for (int p = 0; p < 3; ++p) {
                const u32 aoff = (p == 2) ? CB_AL : CB_AH;
                const u32 boff = (p == 1) ? CB_BL : CB_BH;
                u32 afr[2][4];
                #pragma unroll
                for (int mi = 0; mi < 2; ++mi)
                    ldsm4t(afr[mi][0], afr[mi][1], afr[mi][2], afr[mi][3],
                           buf + aoff + swz256((u32)((kst*16 + (lane & 7)
                                + ((lane >> 4) & 1)*8)*256
                                + (klrow0 + mi*16)*2 + ((lane >> 3) & 1)*16)));
                u32 bfr[4][2];
                #pragma unroll
                for (int nj = 0; nj < 2; ++nj) {
                    u32 r0, r1, r2, r3;
                    ldsm4(r0, r1, r2, r3,
                          buf + boff + swz128((u32)((o0 + nj*16 + (lane & 15))*128
                                              + kst*32 + (lane >> 4)*16)));
                    bfr[nj*2][0] = r0; bfr[nj*2][1] = r2;
                    bfr[nj*2+1][0] = r1; bfr[nj*2+1][1] = r3;
                }
                #pragma unroll
                for (int mi = 0; mi < 2; ++mi)
                    #pragma unroll
                    for (int nt = 0; nt < 4; ++nt)
                        mma_bf(acc[mi][nt], afr[mi], bfr[nt]);
            }
        }
        __syncthreads();
    }

    float* yb = y + (size_t)b*C_DIM*KL;
    #pragma unroll
    for (int mi = 0; mi < 2; ++mi) {
        int kl_r = kl0 + klrow0 + mi*16 + (lane >> 2);
        #pragma unroll
        for (int ni = 0; ni < 4; ++ni) {
            int o = o0 + ni*8 + (lane & 3)*2;
            float b0 = biass[o], b1 = biass[o + 1];
            if (kl_r < KL) {
                yb[(size_t)o*KL + kl_r]         = acc[mi][ni][0] + b0;
                yb[(size_t)(o + 1)*KL + kl_r]   = acc[mi][ni][1] + b1;
            }
            if (kl_r + 8 < KL) {
                yb[(size_t)o*KL + kl_r + 8]       = acc[mi][ni][2] + b0;
                yb[(size_t)(o + 1)*KL + kl_r + 8] = acc[mi][ni][3] + b1;
            }
        }
    }
}

// =============================================================================
extern "C" void kernel_launch(void* const* d_in, const int* in_sizes, int n_in,
                              void* d_out, int out_size) {
    const float* x    = (const float*)d_in[0];
    const float* a0   = (const float*)d_in[1];
    const float* a1   = (const float*)d_in[2];
    const float* W    = (const float*)d_in[3];
    const float* bias = (const float*)d_in[4];
    float* y = (float*)d_out;

    cudaFuncSetAttribute(diffuse_mma, cudaFuncAttributeMaxDynamicSharedMemorySize, D_SMEM);
    cudaFuncSetAttribute(conv_mma,    cudaFuncAttributeMaxDynamicSharedMemorySize, C_SMEM);

    prep_x<<<32768, 256>>>(x);     // B*C*KLP/2 pairs
    prep_a<<<4096, 256>>>(a0, a1); // 2*B*KP*KP/2 pairs
    prep_w<<<40, 256>>>(W);        // 64*320/2 pairs

    diffuse_mma<<<dim3(32, 2, 16), 256, D_SMEM>>>(0);  // A0x, A1x
    diffuse_mma<<<dim3(32, 2, 16), 256, D_SMEM>>>(1);  // A0^2 x, A1^2 x
    conv_mma   <<<dim3(104, 16),   256, C_SMEM>>>(bias, y);
}

// round 14
// speedup vs baseline: 1.4811x; 1.4811x over previous
#include <cuda_runtime.h>
#include <cuda_fp16.h>

typedef unsigned int u32;

#define B_DIM 16
#define C_DIM 64
#define K_DIM 207
#define KL 13248            /* 207*64 */
#define KK 42849            /* 207*207 */
#define KP 256              /* padded k */
#define KLP 16384           /* KP*64 padded plane */

// fp16 scratch (allocation-free rule: __device__ globals)
__device__ __half g_x16[(size_t)B_DIM*C_DIM*KLP];        // x, fp16, k-padded
__device__ __half g_t16[(size_t)4*B_DIM*C_DIM*KLP];      // diffused t, fp16
__device__ __half g_ah[(size_t)2*B_DIM*KP*KP];           // A hi split
__device__ __half g_al[(size_t)2*B_DIM*KP*KP];           // A lo split
__device__ __half g_wh[64*320];
__device__ __half g_wl[64*320];

// ---------------------------------------------------------------- helpers
__device__ __forceinline__ u32 smem_u32(const void* p) {
    u32 a;
    asm("{ .reg .u64 t; cvta.to.shared.u64 t, %1; cvt.u32.u64 %0, t; }" : "=r"(a) : "l"(p));
    return a;
}
// pack {lo: v0, hi: v1} as f16x2
__device__ __forceinline__ u32 cvt2h(float v0, float v1) {
    u32 r; asm("cvt.rn.f16x2.f32 %0, %1, %2;" : "=r"(r) : "f"(v1), "f"(v0)); return r;
}
__device__ __forceinline__ void ldsm4(u32& r0,u32& r1,u32& r2,u32& r3, u32 a){
    asm volatile("ldmatrix.sync.aligned.m8n8.x4.shared.b16 {%0,%1,%2,%3}, [%4];"
        : "=r"(r0),"=r"(r1),"=r"(r2),"=r"(r3) : "r"(a) : "memory");
}
__device__ __forceinline__ void ldsm4t(u32& r0,u32& r1,u32& r2,u32& r3, u32 a){
    asm volatile("ldmatrix.sync.aligned.m8n8.x4.trans.shared.b16 {%0,%1,%2,%3}, [%4];"
        : "=r"(r0),"=r"(r1),"=r"(r2),"=r"(r3) : "r"(a) : "memory");
}
__device__ __forceinline__ void mma_h(float* c, const u32* a, const u32* b){
    asm("mma.sync.aligned.m16n8k16.row.col.f32.f16.f16.f32 "
        "{%0,%1,%2,%3}, {%4,%5,%6,%7}, {%8,%9}, {%0,%1,%2,%3};"
        : "+f"(c[0]),"+f"(c[1]),"+f"(c[2]),"+f"(c[3])
        : "r"(a[0]),"r"(a[1]),"r"(a[2]),"r"(a[3]), "r"(b[0]),"r"(b[1]));
}
// XOR swizzles for 128B / 256B row strides
__device__ __forceinline__ u32 swz128(u32 o){ return o ^ ((o >> 3) & 0x70); }
__device__ __forceinline__ u32 swz256(u32 o){ return o ^ ((o >> 4) & 0x70); }

__device__ __forceinline__ void cpa16(u32 s, const void* g){
    asm volatile("cp.async.cg.shared.global [%0], [%1], 16;" :: "r"(s), "l"(g));
}
#define CP_COMMIT() asm volatile("cp.async.commit_group;" ::: "memory")
#define CP_WAIT0()  asm volatile("cp.async.wait_group 0;" ::: "memory")

// ================= prep: fp32 -> fp16 (hi/lo splits for A, W) ==============
__global__ __launch_bounds__(256) void prep_x(const float* __restrict__ x) {
    size_t pe = ((size_t)blockIdx.x*256 + threadIdx.x) * 2;   // over B*C*KLP
    size_t plane = pe >> 14;
    int r = (int)(pe & 16383), k = r >> 6, l = r & 63;
    float v0 = 0.f, v1 = 0.f;
    if (k < K_DIM) {
        float2 v = *(const float2*)(x + plane*KL + (size_t)k*64 + l);
        v0 = v.x; v1 = v.y;
    }
    *(u32*)(g_x16 + pe) = cvt2h(v0, v1);
}
__global__ __launch_bounds__(256) void prep_a(
    const float* __restrict__ a0, const float* __restrict__ a1) {
    size_t pe = ((size_t)blockIdx.x*256 + threadIdx.x) * 2;   // over 2*B_DIM*KP*KP
    int sb = (int)(pe >> 16);
    int r = (int)(pe & 65535), j = r >> 8, k = r & 255;
    int s = sb >> 4, b = sb & 15;
    const float* A = (s ? a1 : a0) + (size_t)b*KK + (size_t)j*K_DIM;
    float v0 = (j < K_DIM && k     < K_DIM) ? A[k]     : 0.f;
    float v1 = (j < K_DIM && k + 1 < K_DIM) ? A[k + 1] : 0.f;
    float h0 = __half2float(__float2half_rn(v0));
    float h1 = __half2float(__float2half_rn(v1));
    *(u32*)(g_ah + pe) = cvt2h(h0, h1);
    *(u32*)(g_al + pe) = cvt2h(v0 - h0, v1 - h1);
}
__global__ __launch_bounds__(256) void prep_w(const float* __restrict__ W) {
    size_t pe = ((size_t)blockIdx.x*256 + threadIdx.x) * 2;   // over 64*320
    float2 v = *(const float2*)(W + pe);
    float h0 = __half2float(__float2half_rn(v.x));
    float h1 = __half2float(__float2half_rn(v.y));
    *(u32*)(g_wh + pe) = cvt2h(h0, h1);
    *(u32*)(g_wl + pe) = cvt2h(v.x - h0, v.y - h1);
}

// ================= diffuse: t[m][b][c][j][l] = sum_k M[j,k] src[c][k][l] ====
// pass0: src = g_x16 (dst m = 2s); pass1: src = g_t16[m=2s] (dst m = 2s+1).
// CTA: 128 j x 128 n (2 ch x 64 l), 8 warps 64x32. K: 4 chunks of 64 (last 1 step).
// products: (Ah + Al) * X, X fragments reused across both. 2 CTAs/SM.
#define DF_AH 0         /* [128 j][64 k] fp16, 128B rows */
#define DF_AL 16384
#define DF_X  32768     /* [64 k][128 n] fp16, 256B rows */
#define DF_SMEM 49152

__global__ __launch_bounds__(256, 2) void diffuse_mma(int pass)
{
    extern __shared__ char smn[];
    const u32 sb = smem_u32(smn);
    const int tid = threadIdx.x, lane = tid & 31, wid = tid >> 5;
    const int nt = blockIdx.x & 31, jt = blockIdx.x >> 5;
    const int s = blockIdx.y, b = blockIdx.z;
    const int j0 = jt*128;
    const int jm0 = (wid >> 2)*64, n0 = (wid & 3)*32;

    const __half* AH = g_ah + (size_t)(s*B_DIM + b)*KP*KP;
    const __half* AL = g_al + (size_t)(s*B_DIM + b)*KP*KP;
    const __half* X = (pass
        ? g_t16 + (size_t)((2*s)*B_DIM + b)*C_DIM*KLP
        : g_x16 + (size_t)b*C_DIM*KLP) + (size_t)(nt*2)*KLP;

    float acc[4][4][4];
    #pragma unroll
    for (int i = 0; i < 4; ++i)
        #pragma unroll
        for (int j = 0; j < 4; ++j)
            #pragma unroll
            for (int q = 0; q < 4; ++q) acc[i][j][q] = 0.f;

    #pragma unroll 1
    for (int c = 0; c < 4; ++c) {
        const int kc = c*64;
        // ---- stage A hi+lo: 128 rows x 128B each
        #pragma unroll
        for (int it = 0; it < 4; ++it) {
            int e = tid + it*256;
            int j = e >> 3, q = e & 7;
            size_t go = (size_t)(j0 + j)*KP + kc + q*8;
            u32 so = swz128((u32)(j*128 + q*16));
            cpa16(sb + DF_AH + so, AH + go);
            cpa16(sb + DF_AL + so, AL + go);
        }
        // ---- stage X: 64 rows x 256B (2 channels x 128B)
        #pragma unroll
        for (int it = 0; it < 4; ++it) {
            int e = tid + it*256;
            int k = e >> 4, q = e & 15;
            int cl = q >> 3, l8 = (q & 7)*8;
            size_t go = (size_t)cl*KLP + (size_t)(kc + k)*64 + l8;
            cpa16(sb + DF_X + swz256((u32)(k*256 + q*16)), X + go);
        }
        CP_COMMIT(); CP_WAIT0();
        __syncthreads();

        const int nk = (c == 3) ? 1 : 4;
        #pragma unroll 1
        for (int kst = 0; kst < nk; ++kst) {
            u32 xfr[4][2];
            #pragma unroll
            for (int nj = 0; nj < 2; ++nj) {
                u32 r0, r1, r2, r3;
                ldsm4t(r0, r1, r2, r3,
                       sb + DF_X + swz256((u32)((kst*16 + (lane & 15))*256
                                          + (n0 + nj*16)*2 + (lane >> 4)*16)));
                xfr[nj*2][0] = r0; xfr[nj*2][1] = r1;
                xfr[nj*2+1][0] = r2; xfr[nj*2+1][1] = r3;
            }
            #pragma unroll
            for (int p = 0; p < 2; ++p) {
                const u32 aoff = p ? DF_AL : DF_AH;
                u32 afr[4][4];
                #pragma unroll
                for (int mi = 0; mi < 4; ++mi)
                    ldsm4(afr[mi][0], afr[mi][1], afr[mi][2], afr[mi][3],
                          sb + aoff + swz128((u32)((jm0 + mi*16 + (lane & 15))*128
                                             + kst*32 + (lane >> 4)*16)));
                #pragma unroll
                for (int mi = 0; mi < 4; ++mi)
                    #pragma unroll
                    for (int ntc = 0; ntc < 4; ++ntc)
                        mma_h(acc[mi][ntc], afr[mi], xfr[ntc]);
            }
        }
        __syncthreads();
    }

    // ---- epilogue: fp32 acc -> fp16 t (unconditional; pad rows are zeros)
    const int cl = n0 >> 6, lb = n0 & 63;
    __half* T = g_t16 + ((size_t)((2*s + pass)*B_DIM + b)*C_DIM + nt*2 + cl)*KLP;
    #pragma unroll
    for (int mi = 0; mi < 4; ++mi) {
        int r0 = j0 + jm0 + mi*16 + (lane >> 2);
        #pragma unroll
        for (int ntc = 0; ntc < 4; ++ntc) {
            int l = lb + ntc*8 + (lane & 3)*2;
            *(u32*)(T + (size_t)r0*64 + l)       = cvt2h(acc[mi][ntc][0], acc[mi][ntc][1]);
            *(u32*)(T + (size_t)(r0 + 8)*64 + l) = cvt2h(acc[mi][ntc][2], acc[mi][ntc][3]);
        }
    }
}

// ================= conv: y[b][o][kl] = sum_i W[o,i] H[i][kl] + bias[o] ======
// H blocks of 64 i: [g_x16 | g_t16 m=0..3]. CTA: 128 kl x 64 o, warp 32x32.
// products: (Wh + Wl) * H, H fragments reused. 2 CTAs/SM.
#define CV_A  0         /* [64 i][128 kl] fp16, 256B rows */
#define CV_WH 16384     /* [64 o][64 i] fp16, 128B rows */
#define CV_WL 24576
#define CV_SMEM 32768

__global__ __launch_bounds__(256, 2) void conv_mma(
    const float* __restrict__ bias, float* __restrict__ y)
{
    extern __shared__ char smn[];
    __shared__ float biass[64];
    const u32 sb = smem_u32(smn);
    const int tid = threadIdx.x, lane = tid & 31, wid = tid >> 5;
    const int b = blockIdx.y;
    const int kl0 = blockIdx.x * 128;
    const int klrow0 = (wid >> 1)*32, o0 = (wid & 1)*32;

    if (tid < 64) biass[tid] = bias[tid];

    float acc[2][4][4];
    #pragma unroll
    for (int i = 0; i < 2; ++i)
        #pragma unroll
        for (int j = 0; j < 4; ++j)
            #pragma unroll
            for (int q = 0; q < 4; ++q) acc[i][j][q] = 0.f;

    #pragma unroll 1
    for (int ch = 0; ch < 5; ++ch) {
        const __half* Hp = (ch == 0)
            ? g_x16 + (size_t)b*C_DIM*KLP
            : g_t16 + (size_t)((ch - 1)*B_DIM + b)*C_DIM*KLP;
        __syncthreads();   // previous chunk's LDSMs done before overwrite
        // ---- stage A (H^T slab): 64 rows x 256B
        #pragma unroll
        for (int it = 0; it < 4; ++it) {
            int e = tid + it*256;
            int i = e >> 4, q = e & 15;
            size_t go = (size_t)i*KLP + kl0 + q*8;
            cpa16(sb + CV_A + swz256((u32)(i*256 + q*16)), Hp + go);
        }
        // ---- stage W hi+lo: 64 rows x 128B each
        #pragma unroll
        for (int it = 0; it < 2; ++it) {
            int e = tid + it*256;
            int o = e >> 3, q = e & 7;
            size_t go = (size_t)o*320 + ch*64 + q*8;
            u32 so = swz128((u32)(o*128 + q*16));
            cpa16(sb + CV_WH + so, g_wh + go);
            cpa16(sb + CV_WL + so, g_wl + go);
        }
        CP_COMMIT(); CP_WAIT0();
        __syncthreads();

        #pragma unroll 1
        for (int kst = 0; kst < 4; ++kst) {
            u32 afr[2][4];
            #pragma unroll
            for (int mi = 0; mi < 2; ++mi)
                ldsm4t(afr[mi][0], afr[mi][1], afr[mi][2], afr[mi][3],
                       sb + CV_A + swz256((u32)((kst*16 + (lane & 7)
                            + ((lane >> 4) & 1)*8)*256
                            + (klrow0 + mi*16)*2 + ((lane >> 3) & 1)*16)));
            #pragma unroll
            for (int p = 0; p < 2; ++p) {
                const u32 boff = p ? CV_WL : CV_WH;
                u32 bfr[4][2];
                #pragma unroll
                for (int nj = 0; nj < 2; ++nj) {
                    u32 r0, r1, r2, r3;
                    ldsm4(r0, r1, r2, r3,
                          sb + boff + swz128((u32)((o0 + nj*16 + (lane & 15))*128
                                             + kst*32 + (lane >> 4)*16)));
                    bfr[nj*2][0] = r0; bfr[nj*2][1] = r2;
                    bfr[nj*2+1][0] = r1; bfr[nj*2+1][1] = r3;
                }
                #pragma unroll
                for (int mi = 0; mi < 2; ++mi)
                    #pragma unroll
                    for (int ntc = 0; ntc < 4; ++ntc)
                        mma_h(acc[mi][ntc], afr[mi], bfr[ntc]);
            }
        }
    }

    float* yb = y + (size_t)b*C_DIM*KL;
    #pragma unroll
    for (int mi = 0; mi < 2; ++mi) {
        int kl_r = kl0 + klrow0 + mi*16 + (lane >> 2);
        #pragma unroll
        for (int ni = 0; ni < 4; ++ni) {
            int o = o0 + ni*8 + (lane & 3)*2;
            float b0 = biass[o], b1 = biass[o + 1];
            if (kl_r < KL) {
                yb[(size_t)o*KL + kl_r]         = acc[mi][ni][0] + b0;
                yb[(size_t)(o + 1)*KL + kl_r]   = acc[mi][ni][1] + b1;
            }
            if (kl_r + 8 < KL) {
                yb[(size_t)o*KL + kl_r + 8]       = acc[mi][ni][2] + b0;
                yb[(size_t)(o + 1)*KL + kl_r + 8] = acc[mi][ni][3] + b1;
            }
        }
    }
}

// =============================================================================
extern "C" void kernel_launch(void* const* d_in, const int* in_sizes, int n_in,
                              void* d_out, int out_size) {
    const float* x    = (const float*)d_in[0];
    const float* a0   = (const float*)d_in[1];
    const float* a1   = (const float*)d_in[2];
    const float* W    = (const float*)d_in[3];
    const float* bias = (const float*)d_in[4];
    float* y = (float*)d_out;

    cudaFuncSetAttribute(diffuse_mma, cudaFuncAttributeMaxDynamicSharedMemorySize, DF_SMEM);
    cudaFuncSetAttribute(conv_mma,    cudaFuncAttributeMaxDynamicSharedMemorySize, CV_SMEM);

    prep_x<<<32768, 256>>>(x);      // B*C*KLP/2 pairs
    prep_a<<<4096, 256>>>(a0, a1);  // 2*B*KP*KP/2 pairs
    prep_w<<<40, 256>>>(W);         // 64*320/2 pairs

    diffuse_mma<<<dim3(64, 2, 16), 256, DF_SMEM>>>(0);  // A0x, A1x
    diffuse_mma<<<dim3(64, 2, 16), 256, DF_SMEM>>>(1);  // A0^2 x, A1^2 x
    conv_mma   <<<dim3(104, 16),   256, CV_SMEM>>>(bias, y);
}

// round 15
// speedup vs baseline: 1.7821x; 1.2033x over previous
#include <cuda_runtime.h>
#include <cuda_fp16.h>

typedef unsigned int u32;

#define B_DIM 16
#define C_DIM 64
#define K_DIM 207
#define KL 13248            /* 207*64 */
#define KK 42849            /* 207*207 */
#define KP 256              /* padded k */
#define KLP 16384           /* KP*64 padded plane */

// fp16 scratch (allocation-free rule: __device__ globals; zero-init at load,
// rows never written stay zero — relied on for j-padding in g_t16)
__device__ __half g_x16[(size_t)B_DIM*C_DIM*KLP];
__device__ __half g_t16[(size_t)4*B_DIM*C_DIM*KLP];
__device__ __half g_ah[(size_t)2*B_DIM*KP*KP];
__device__ __half g_al[(size_t)2*B_DIM*KP*KP];
__device__ __half g_wh[64*320];

// ---------------------------------------------------------------- helpers
__device__ __forceinline__ u32 smem_u32(const void* p) {
    u32 a;
    asm("{ .reg .u64 t; cvta.to.shared.u64 t, %1; cvt.u32.u64 %0, t; }" : "=r"(a) : "l"(p));
    return a;
}
// pack {lo: v0, hi: v1} as f16x2
__device__ __forceinline__ u32 cvt2h(float v0, float v1) {
    u32 r; asm("cvt.rn.f16x2.f32 %0, %1, %2;" : "=r"(r) : "f"(v1), "f"(v0)); return r;
}
__device__ __forceinline__ void ldsm4(u32& r0,u32& r1,u32& r2,u32& r3, u32 a){
    asm volatile("ldmatrix.sync.aligned.m8n8.x4.shared.b16 {%0,%1,%2,%3}, [%4];"
        : "=r"(r0),"=r"(r1),"=r"(r2),"=r"(r3) : "r"(a) : "memory");
}
__device__ __forceinline__ void ldsm4t(u32& r0,u32& r1,u32& r2,u32& r3, u32 a){
    asm volatile("ldmatrix.sync.aligned.m8n8.x4.trans.shared.b16 {%0,%1,%2,%3}, [%4];"
        : "=r"(r0),"=r"(r1),"=r"(r2),"=r"(r3) : "r"(a) : "memory");
}
__device__ __forceinline__ void mma_h(float* c, const u32* a, const u32* b){
    asm("mma.sync.aligned.m16n8k16.row.col.f32.f16.f16.f32 "
        "{%0,%1,%2,%3}, {%4,%5,%6,%7}, {%8,%9}, {%0,%1,%2,%3};"
        : "+f"(c[0]),"+f"(c[1]),"+f"(c[2]),"+f"(c[3])
        : "r"(a[0]),"r"(a[1]),"r"(a[2]),"r"(a[3]), "r"(b[0]),"r"(b[1]));
}
// XOR swizzles for 128B / 256B row strides
__device__ __forceinline__ u32 swz128(u32 o){ return o ^ ((o >> 3) & 0x70); }
__device__ __forceinline__ u32 swz256(u32 o){ return o ^ ((o >> 4) & 0x70); }

__device__ __forceinline__ void cpa16(u32 s, const void* g){
    asm volatile("cp.async.cg.shared.global [%0], [%1], 16;" :: "r"(s), "l"(g));
}
#define CP_COMMIT() asm volatile("cp.async.commit_group;" ::: "memory")
#define CP_WAIT1()  asm volatile("cp.async.wait_group 1;" ::: "memory")
#define CP_WAIT0()  asm volatile("cp.async.wait_group 0;" ::: "memory")

// ================= prep: fp32 -> fp16 (hi/lo split for A only) ==============
__global__ __launch_bounds__(256) void prep_x(const float* __restrict__ x) {
    size_t pe = ((size_t)blockIdx.x*256 + threadIdx.x) * 2;   // over B*C*KLP
    size_t plane = pe >> 14;
    int r = (int)(pe & 16383), k = r >> 6, l = r & 63;
    float v0 = 0.f, v1 = 0.f;
    if (k < K_DIM) {
        float2 v = *(const float2*)(x + plane*KL + (size_t)k*64 + l);
        v0 = v.x; v1 = v.y;
    }
    *(u32*)(g_x16 + pe) = cvt2h(v0, v1);
}
__global__ __launch_bounds__(256) void prep_a(
    const float* __restrict__ a0, const float* __restrict__ a1) {
    size_t pe = ((size_t)blockIdx.x*256 + threadIdx.x) * 2;   // over 2*B_DIM*KP*KP
    int sb = (int)(pe >> 16);
    int r = (int)(pe & 65535), j = r >> 8, k = r & 255;
    int s = sb >> 4, b = sb & 15;
    const float* A = (s ? a1 : a0) + (size_t)b*KK + (size_t)j*K_DIM;
    float v0 = (j < K_DIM && k     < K_DIM) ? A[k]     : 0.f;
    float v1 = (j < K_DIM && k + 1 < K_DIM) ? A[k + 1] : 0.f;
    float h0 = __half2float(__float2half_rn(v0));
    float h1 = __half2float(__float2half_rn(v1));
    *(u32*)(g_ah + pe) = cvt2h(h0, h1);
    *(u32*)(g_al + pe) = cvt2h(v0 - h0, v1 - h1);
}
__global__ __launch_bounds__(256) void prep_w(const float* __restrict__ W) {
    size_t pe = ((size_t)blockIdx.x*256 + threadIdx.x) * 2;   // over 64*320
    float2 v = *(const float2*)(W + pe);
    *(u32*)(g_wh + pe) = cvt2h(v.x, v.y);
}

// ================= diffuse: t[m][b][c][j][l] = sum_k M[j,k] src[c][k][l] ====
// pass0: src = g_x16 (dst m = 2s); pass1: src = g_t16[m=2s] (dst m = 2s+1).
// CTA: 128 j x 128 n (2 ch x 64 l), 8 warps 64x32, double-buffered K chunks of 64.
// (Ah + Al) * X with X fragments reused. Partial warps (j beyond 207) do 1 frag.
#define DF_AH 0         /* [128 j][64 k] fp16, 128B rows */
#define DF_AL 16384
#define DF_X  32768     /* [64 k][128 n] fp16, 256B rows */
#define DF_SZ 49152
#define DF_SMEM (2*DF_SZ)

__global__ __launch_bounds__(256, 2) void diffuse_mma(int pass)
{
    extern __shared__ char smn[];
    const u32 sb = smem_u32(smn);
    const int tid = threadIdx.x, lane = tid & 31, wid = tid >> 5;
    const int nt = blockIdx.x & 31, jt = blockIdx.x >> 5;
    const int s = blockIdx.y, b = blockIdx.z;
    const int j0 = jt*128;
    const int jm0 = (wid >> 2)*64, n0 = (wid & 3)*32;
    const bool full = (j0 + jm0 + 64 <= 208);   // all 4 M-frags contain real rows

    const __half* AH = g_ah + (size_t)(s*B_DIM + b)*KP*KP;
    const __half* AL = g_al + (size_t)(s*B_DIM + b)*KP*KP;
    const __half* X = (pass
        ? g_t16 + (size_t)((2*s)*B_DIM + b)*C_DIM*KLP
        : g_x16 + (size_t)b*C_DIM*KLP) + (size_t)(nt*2)*KLP;

    auto stage = [&](int chunk, u32 sbuf){
        const int kc = chunk*64;
        #pragma unroll
        for (int it = 0; it < 4; ++it) {          // A hi+lo: 128 rows x 128B each
            int e = tid + it*256;
            int j = e >> 3, q = e & 7;
            size_t go = (size_t)(j0 + j)*KP + kc + q*8;
            u32 so = swz128((u32)(j*128 + q*16));
            cpa16(sbuf + DF_AH + so, AH + go);
            cpa16(sbuf + DF_AL + so, AL + go);
        }
        #pragma unroll
        for (int it = 0; it < 4; ++it) {          // X: 64 rows x 256B
            int e = tid + it*256;
            int k = e >> 4, q = e & 15;
            int cl = q >> 3, l8 = (q & 7)*8;
            size_t go = (size_t)cl*KLP + (size_t)(kc + k)*64 + l8;
            cpa16(sbuf + DF_X + swz256((u32)(k*256 + q*16)), X + go);
        }
    };

    float acc[4][4][4];
    #pragma unroll
    for (int i = 0; i < 4; ++i)
        #pragma unroll
        for (int j = 0; j < 4; ++j)
            #pragma unroll
            for (int q = 0; q < 4; ++q) acc[i][j][q] = 0.f;

    stage(0, sb); CP_COMMIT();
    #pragma unroll 1
    for (int c = 0; c < 4; ++c) {
        if (c < 3) { stage(c + 1, sb + ((c + 1) & 1)*DF_SZ); CP_COMMIT(); CP_WAIT1(); }
        else       { CP_WAIT0(); }
        __syncthreads();
        const u32 buf = sb + (c & 1)*DF_SZ;
        const int nk = (c == 3) ? 1 : 4;
        #pragma unroll 1
        for (int kst = 0; kst < nk; ++kst) {
            u32 xfr[4][2];
            #pragma unroll
            for (int nj = 0; nj < 2; ++nj) {
                u32 r0, r1, r2, r3;
                ldsm4t(r0, r1, r2, r3,
                       buf + DF_X + swz256((u32)((kst*16 + (lane & 15))*256
                                           + (n0 + nj*16)*2 + (lane >> 4)*16)));
                xfr[nj*2][0] = r0; xfr[nj*2][1] = r1;
                xfr[nj*2+1][0] = r2; xfr[nj*2+1][1] = r3;
            }
            #pragma unroll
            for (int p = 0; p < 2; ++p) {
                const u32 aoff = p ? DF_AL : DF_AH;
                if (full) {
                    u32 afr[4][4];
                    #pragma unroll
                    for (int mi = 0; mi < 4; ++mi)
                        ldsm4(afr[mi][0], afr[mi][1], afr[mi][2], afr[mi][3],
                              buf + aoff + swz128((u32)((jm0 + mi*16 + (lane & 15))*128
                                                 + kst*32 + (lane >> 4)*16)));
                    #pragma unroll
                    for (int mi = 0; mi < 4; ++mi)
                        #pragma unroll
                        for (int ntc = 0; ntc < 4; ++ntc)
                            mma_h(acc[mi][ntc], afr[mi], xfr[ntc]);
                } else {
                    u32 afr[4];
                    ldsm4(afr[0], afr[1], afr[2], afr[3],
                          buf + aoff + swz128((u32)((jm0 + (lane & 15))*128
                                             + kst*32 + (lane >> 4)*16)));
                    #pragma unroll
                    for (int ntc = 0; ntc < 4; ++ntc)
                        mma_h(acc[0][ntc], afr, xfr[ntc]);
                }
            }
        }
        __syncthreads();
    }

    // ---- epilogue: fp32 acc -> fp16 t; partial warps store frag 0 only
    // (their skipped rows >= 208 remain zero from static init)
    const int cl = n0 >> 6, lb = n0 & 63;
    __half* T = g_t16 + ((size_t)((2*s + pass)*B_DIM + b)*C_DIM + nt*2 + cl)*KLP;
    const int MM = full ? 4 : 1;
    #pragma unroll
    for (int mi = 0; mi < 4; ++mi) {
        if (mi >= MM) break;
        int r0 = j0 + jm0 + mi*16 + (lane >> 2);
        #pragma unroll
        for (int ntc = 0; ntc < 4; ++ntc) {
            int l = lb + ntc*8 + (lane & 3)*2;
            *(u32*)(T + (size_t)r0*64 + l)       = cvt2h(acc[mi][ntc][0], acc[mi][ntc][1]);
            *(u32*)(T + (size_t)(r0 + 8)*64 + l) = cvt2h(acc[mi][ntc][2], acc[mi][ntc][3]);
        }
    }
}

// ================= conv: y[b][o][kl] = sum_i W[o,i] H[i][kl] + bias[o] ======
// H blocks of 64 i: [g_x16 | g_t16 m=0..3]. CTA: 128 kl x 64 o, warp 32x32.
// single fp16 product (W quantized). Double-buffered. 2 CTAs/SM.
#define CV_A  0         /* [64 i][128 kl] fp16, 256B rows */
#define CV_W  16384     /* [64 o][64 i] fp16, 128B rows */
#define CV_SZ 24576
#define CV_SMEM (2*CV_SZ)

__global__ __launch_bounds__(256, 2) void conv_mma(
    const float* __restrict__ bias, float* __restrict__ y)
{
    extern __shared__ char smn[];
    __shared__ float biass[64];
    const u32 sb = smem_u32(smn);
    const int tid = threadIdx.x, lane = tid & 31, wid = tid >> 5;
    const int b = blockIdx.y;
    const int kl0 = blockIdx.x * 128;
    const int klrow0 = (wid >> 1)*32, o0 = (wid & 1)*32;

    if (tid < 64) biass[tid] = bias[tid];

    auto stage = [&](int ch, u32 sbuf){
        const __half* Hp = (ch == 0)
            ? g_x16 + (size_t)b*C_DIM*KLP
            : g_t16 + (size_t)((ch - 1)*B_DIM + b)*C_DIM*KLP;
        #pragma unroll
        for (int it = 0; it < 4; ++it) {          // A (H^T slab): 64 rows x 256B
            int e = tid + it*256;
            int i = e >> 4, q = e & 15;
            size_t go = (size_t)i*KLP + kl0 + q*8;
            cpa16(sbuf + CV_A + swz256((u32)(i*256 + q*16)), Hp + go);
        }
        #pragma unroll
        for (int it = 0; it < 2; ++it) {          // W: 64 rows x 128B
            int e = tid + it*256;
            int o = e >> 3, q = e & 7;
            size_t go = (size_t)o*320 + ch*64 + q*8;
            cpa16(sbuf + CV_W + swz128((u32)(o*128 + q*16)), g_wh + go);
        }
    };

    float acc[2][4][4];
    #pragma unroll
    for (int i = 0; i < 2; ++i)
        #pragma unroll
        for (int j = 0; j < 4; ++j)
            #pragma unroll
            for (int q = 0; q < 4; ++q) acc[i][j][q] = 0.f;

    stage(0, sb); CP_COMMIT();
    #pragma unroll 1
    for (int c = 0; c < 5; ++c) {
        if (c < 4) { stage(c + 1, sb + ((c + 1) & 1)*CV_SZ); CP_COMMIT(); CP_WAIT1(); }
        else       { CP_WAIT0(); }
        __syncthreads();
        const u32 buf = sb + (c & 1)*CV_SZ;
        #pragma unroll 1
        for (int kst = 0; kst < 4; ++kst) {
            u32 afr[2][4];
            #pragma unroll
            for (int mi = 0; mi < 2; ++mi)
                ldsm4t(afr[mi][0], afr[mi][1], afr[mi][2], afr[mi][3],
                       buf + CV_A + swz256((u32)((kst*16 + (lane & 7)
                            + ((lane >> 4) & 1)*8)*256
                            + (klrow0 + mi*16)*2 + ((lane >> 3) & 1)*16)));
            u32 bfr[4][2];
            #pragma unroll
            for (int nj = 0; nj < 2; ++nj) {
                u32 r0, r1, r2, r3;
                ldsm4(r0, r1, r2, r3,
                      buf + CV_W + swz128((u32)((o0 + nj*16 + (lane & 15))*128
                                         + kst*32 + (lane >> 4)*16)));
                bfr[nj*2][0] = r0; bfr[nj*2][1] = r2;
                bfr[nj*2+1][0] = r1; bfr[nj*2+1][1] = r3;
            }
            #pragma unroll
            for (int mi = 0; mi < 2; ++mi)
                #pragma unroll
                for (int ntc = 0; ntc < 4; ++ntc)
                    mma_h(acc[mi][ntc], afr[mi], bfr[ntc]);
        }
        __syncthreads();
    }

    float* yb = y + (size_t)b*C_DIM*KL;
    #pragma unroll
    for (int mi = 0; mi < 2; ++mi) {
        int kl_r = kl0 + klrow0 + mi*16 + (lane >> 2);
        #pragma unroll
        for (int ni = 0; ni < 4; ++ni) {
            int o = o0 + ni*8 + (lane & 3)*2;
            float b0 = biass[o], b1 = biass[o + 1];
            if (kl_r < KL) {
                yb[(size_t)o*KL + kl_r]         = acc[mi][ni][0] + b0;
                yb[(size_t)(o + 1)*KL + kl_r]   = acc[mi][ni][1] + b1;
            }
            if (kl_r + 8 < KL) {
                yb[(size_t)o*KL + kl_r + 8]       = acc[mi][ni][2] + b0;
                yb[(size_t)(o + 1)*KL + kl_r + 8] = acc[mi][ni][3] + b1;
            }
        }
    }
}

// =============================================================================
extern "C" void kernel_launch(void* const* d_in, const int* in_sizes, int n_in,
                              void* d_out, int out_size) {
    const float* x    = (const float*)d_in[0];
    const float* a0   = (const float*)d_in[1];
    const float* a1   = (const float*)d_in[2];
    const float* W    = (const float*)d_in[3];
    const float* bias = (const float*)d_in[4];
    float* y = (float*)d_out;

    cudaFuncSetAttribute(diffuse_mma, cudaFuncAttributeMaxDynamicSharedMemorySize, DF_SMEM);
    cudaFuncSetAttribute(conv_mma,    cudaFuncAttributeMaxDynamicSharedMemorySize, CV_SMEM);

    prep_x<<<32768, 256>>>(x);      // B*C*KLP/2 pairs
    prep_a<<<4096, 256>>>(a0, a1);  // 2*B*KP*KP/2 pairs
    prep_w<<<40, 256>>>(W);         // 64*320/2 pairs

    diffuse_mma<<<dim3(64, 2, 16), 256, DF_SMEM>>>(0);  // A0x, A1x
    diffuse_mma<<<dim3(64, 2, 16), 256, DF_SMEM>>>(1);  // A0^2 x, A1^2 x
    conv_mma   <<<dim3(104, 16),   256, CV_SMEM>>>(bias, y);
}

// round 16
// speedup vs baseline: 1.8991x; 1.0656x over previous
#include <cuda_runtime.h>
#include <cuda_fp16.h>

typedef unsigned int u32;

#define B_DIM 16
#define C_DIM 64
#define K_DIM 207
#define KL 13248            /* 207*64 */
#define KK 42849            /* 207*207 */
#define KP 256              /* padded k */
#define KLP 16384           /* KP*64 padded plane */

// fp16 scratch (allocation-free rule: __device__ globals; zero-init at load,
// rows never written stay zero — relied on for j/k padding)
__device__ __half g_x16[(size_t)B_DIM*C_DIM*KLP];
__device__ __half g_t16[(size_t)4*B_DIM*C_DIM*KLP];
__device__ __half g_ah[(size_t)2*B_DIM*KP*KP];
__device__ __half g_al[(size_t)2*B_DIM*KP*KP];
__device__ __half g_wh[64*320];

// ---------------------------------------------------------------- helpers
__device__ __forceinline__ u32 smem_u32(const void* p) {
    u32 a;
    asm("{ .reg .u64 t; cvta.to.shared.u64 t, %1; cvt.u32.u64 %0, t; }" : "=r"(a) : "l"(p));
    return a;
}
// pack {lo: v0, hi: v1} as f16x2
__device__ __forceinline__ u32 cvt2h(float v0, float v1) {
    u32 r; asm("cvt.rn.f16x2.f32 %0, %1, %2;" : "=r"(r) : "f"(v1), "f"(v0)); return r;
}
__device__ __forceinline__ void ldsm4(u32& r0,u32& r1,u32& r2,u32& r3, u32 a){
    asm volatile("ldmatrix.sync.aligned.m8n8.x4.shared.b16 {%0,%1,%2,%3}, [%4];"
        : "=r"(r0),"=r"(r1),"=r"(r2),"=r"(r3) : "r"(a) : "memory");
}
__device__ __forceinline__ void ldsm4t(u32& r0,u32& r1,u32& r2,u32& r3, u32 a){
    asm volatile("ldmatrix.sync.aligned.m8n8.x4.trans.shared.b16 {%0,%1,%2,%3}, [%4];"
        : "=r"(r0),"=r"(r1),"=r"(r2),"=r"(r3) : "r"(a) : "memory");
}
__device__ __forceinline__ void mma_h(float* c, const u32* a, const u32* b){
    asm("mma.sync.aligned.m16n8k16.row.col.f32.f16.f16.f32 "
        "{%0,%1,%2,%3}, {%4,%5,%6,%7}, {%8,%9}, {%0,%1,%2,%3};"
        : "+f"(c[0]),"+f"(c[1]),"+f"(c[2]),"+f"(c[3])
        : "r"(a[0]),"r"(a[1]),"r"(a[2]),"r"(a[3]), "r"(b[0]),"r"(b[1]));
}
// XOR swizzles for 128B / 512B row strides
__device__ __forceinline__ u32 swz128(u32 o){ return o ^ ((o >> 3) & 0x70); }
__device__ __forceinline__ u32 swz512(u32 o){ return o ^ ((o >> 5) & 0x70); }

__device__ __forceinline__ void cpa16(u32 s, const void* g){
    asm volatile("cp.async.cg.shared.global [%0], [%1], 16;" :: "r"(s), "l"(g));
}
#define CP_COMMIT() asm volatile("cp.async.commit_group;" ::: "memory")
#define CP_WAIT1()  asm volatile("cp.async.wait_group 1;" ::: "memory")
#define CP_WAIT0()  asm volatile("cp.async.wait_group 0;" ::: "memory")

// ================= prep: fp32 -> fp16 (hi/lo split for A only) ==============
__global__ __launch_bounds__(256) void prep_x(const float* __restrict__ x) {
    size_t pe = ((size_t)blockIdx.x*256 + threadIdx.x) * 2;   // over B*C*KLP
    size_t plane = pe >> 14;
    int r = (int)(pe & 16383), k = r >> 6, l = r & 63;
    float v0 = 0.f, v1 = 0.f;
    if (k < K_DIM) {
        float2 v = *(const float2*)(x + plane*KL + (size_t)k*64 + l);
        v0 = v.x; v1 = v.y;
    }
    *(u32*)(g_x16 + pe) = cvt2h(v0, v1);
}
__global__ __launch_bounds__(256) void prep_a(
    const float* __restrict__ a0, const float* __restrict__ a1) {
    size_t pe = ((size_t)blockIdx.x*256 + threadIdx.x) * 2;   // over 2*B_DIM*KP*KP
    int sb = (int)(pe >> 16);
    int r = (int)(pe & 65535), j = r >> 8, k = r & 255;
    int s = sb >> 4, b = sb & 15;
    const float* A = (s ? a1 : a0) + (size_t)b*KK + (size_t)j*K_DIM;
    float v0 = (j < K_DIM && k     < K_DIM) ? A[k]     : 0.f;
    float v1 = (j < K_DIM && k + 1 < K_DIM) ? A[k + 1] : 0.f;
    float h0 = __half2float(__float2half_rn(v0));
    float h1 = __half2float(__float2half_rn(v1));
    *(u32*)(g_ah + pe) = cvt2h(h0, h1);
    *(u32*)(g_al + pe) = cvt2h(v0 - h0, v1 - h1);
}
__global__ __launch_bounds__(256) void prep_w(const float* __restrict__ W) {
    size_t pe = ((size_t)blockIdx.x*256 + threadIdx.x) * 2;   // over 64*320
    float2 v = *(const float2*)(W + pe);
    *(u32*)(g_wh + pe) = cvt2h(v.x, v.y);
}

// ================= diffuse: t[m][b][c][j][l] = sum_k M[j,k] src[c][k][l] ====
// pass0: src = g_x16, dst m=2s, (Ah+Al)*X; pass1: src = g_t16[2s], dst m=2s+1, Ah*X.
// CTA: 128 j x 256 n (4 ch x 64 l), 8 warps 64x64. DB'd K chunks of 64. 1 CTA/SM.
#define DF_AH 0         /* [128 j][64 k] fp16, 128B rows */
#define DF_AL 16384
#define DF_X  32768     /* [64 k][256 n] fp16, 512B rows */
#define DF_SZ 65536
#define DF_SMEM (2*DF_SZ)

__global__ __launch_bounds__(256, 1) void diffuse_mma(int pass)
{
    extern __shared__ char smn[];
    const u32 sb = smem_u32(smn);
    const int tid = threadIdx.x, lane = tid & 31, wid = tid >> 5;
    const int nt = blockIdx.x & 15, jt = blockIdx.x >> 4;
    const int s = blockIdx.y, b = blockIdx.z;
    const int j0 = jt*128;
    const int jm0 = (wid >> 2)*64, n0 = (wid & 3)*64, warp_n = wid & 3;
    const bool full = (j0 + jm0 + 64 <= 208);   // all 4 M-frags contain real rows
    const int np = pass ? 1 : 2;

    const __half* AH = g_ah + (size_t)(s*B_DIM + b)*KP*KP;
    const __half* AL = g_al + (size_t)(s*B_DIM + b)*KP*KP;
    const __half* X = (pass
        ? g_t16 + (size_t)((2*s)*B_DIM + b)*C_DIM*KLP
        : g_x16 + (size_t)b*C_DIM*KLP) + (size_t)(nt*4)*KLP;

    auto stage = [&](int chunk, u32 sbuf){
        const int kc = chunk*64;
        #pragma unroll
        for (int it = 0; it < 4; ++it) {          // A: 128 rows x 128B (hi, +lo p0)
            int e = tid + it*256;
            int j = e >> 3, q = e & 7;
            size_t go = (size_t)(j0 + j)*KP + kc + q*8;
            u32 so = swz128((u32)(j*128 + q*16));
            cpa16(sbuf + DF_AH + so, AH + go);
            if (!pass) cpa16(sbuf + DF_AL + so, AL + go);
        }
        #pragma unroll
        for (int it = 0; it < 8; ++it) {          // X: 64 rows x 512B (4 ch x 128B)
            int e = tid + it*256;
            int k = e >> 5, q = e & 31;
            int cl = q >> 3, l8 = (q & 7)*8;
            size_t go = (size_t)cl*KLP + (size_t)(kc + k)*64 + l8;
            cpa16(sbuf + DF_X + swz512((u32)(k*512 + q*16)), X + go);
        }
    };

    float acc[4][8][4];
    #pragma unroll
    for (int i = 0; i < 4; ++i)
        #pragma unroll
        for (int j = 0; j < 8; ++j)
            #pragma unroll
            for (int q = 0; q < 4; ++q) acc[i][j][q] = 0.f;

    stage(0, sb); CP_COMMIT();
    #pragma unroll 1
    for (int c = 0; c < 4; ++c) {
        if (c < 3) { stage(c + 1, sb + ((c + 1) & 1)*DF_SZ); CP_COMMIT(); CP_WAIT1(); }
        else       { CP_WAIT0(); }
        __syncthreads();
        const u32 buf = sb + (c & 1)*DF_SZ;
        const int nk = (c == 3) ? 1 : 4;
        #pragma unroll 1
        for (int kst = 0; kst < nk; ++kst) {
            // X fragments loaded ONCE, reused across both A products
            u32 xfr[8][2];
            #pragma unroll
            for (int nj = 0; nj < 4; ++nj) {
                u32 r0, r1, r2, r3;
                ldsm4t(r0, r1, r2, r3,
                       buf + DF_X + swz512((u32)((kst*16 + (lane & 15))*512
                                           + (n0 + nj*16)*2 + (lane >> 4)*16)));
                xfr[nj*2][0] = r0; xfr[nj*2][1] = r1;
                xfr[nj*2+1][0] = r2; xfr[nj*2+1][1] = r3;
            }
            for (int p = 0; p < np; ++p) {
                const u32 aoff = p ? DF_AL : DF_AH;
                if (full) {
                    u32 afr[4][4];
                    #pragma unroll
                    for (int mi = 0; mi < 4; ++mi)
                        ldsm4(afr[mi][0], afr[mi][1], afr[mi][2], afr[mi][3],
                              buf + aoff + swz128((u32)((jm0 + mi*16 + (lane & 15))*128
                                                 + kst*32 + (lane >> 4)*16)));
                    #pragma unroll
                    for (int mi = 0; mi < 4; ++mi)
                        #pragma unroll
                        for (int ntc = 0; ntc < 8; ++ntc)
                            mma_h(acc[mi][ntc], afr[mi], xfr[ntc]);
                } else {
                    u32 afr[4];
                    ldsm4(afr[0], afr[1], afr[2], afr[3],
                          buf + aoff + swz128((u32)((jm0 + (lane & 15))*128
                                             + kst*32 + (lane >> 4)*16)));
                    #pragma unroll
                    for (int ntc = 0; ntc < 8; ++ntc)
                        mma_h(acc[0][ntc], afr, xfr[ntc]);
                }
            }
        }
        __syncthreads();
    }

    // ---- epilogue: fp32 acc -> fp16 t; warp_n owns one full channel
    __half* T = g_t16 + ((size_t)((2*s + pass)*B_DIM + b)*C_DIM + nt*4 + warp_n)*KLP;
    const int MM = full ? 4 : 1;
    #pragma unroll
    for (int mi = 0; mi < 4; ++mi) {
        if (mi >= MM) break;
        int r0 = j0 + jm0 + mi*16 + (lane >> 2);
        #pragma unroll
        for (int ntc = 0; ntc < 8; ++ntc) {
            int l = ntc*8 + (lane & 3)*2;
            *(u32*)(T + (size_t)r0*64 + l)       = cvt2h(acc[mi][ntc][0], acc[mi][ntc][1]);
            *(u32*)(T + (size_t)(r0 + 8)*64 + l) = cvt2h(acc[mi][ntc][2], acc[mi][ntc][3]);
        }
    }
}

// ================= conv: y[b][o][kl] = sum_i W[o,i] H[i][kl] + bias[o] ======
// H blocks of 64 i: [g_x16 | g_t16 m=0..3]. CTA: 256 kl x 64 o, 4 warps 64x64.
// single fp16 product. Double-buffered. 2 CTAs/SM.
#define CV_A  0         /* [64 i][256 kl] fp16, 512B rows */
#define CV_W  32768     /* [64 o][64 i] fp16, 128B rows */
#define CV_SZ 40960
#define CV_SMEM (2*CV_SZ)

__global__ __launch_bounds__(128, 2) void conv_mma(
    const float* __restrict__ bias, float* __restrict__ y)
{
    extern __shared__ char smn[];
    __shared__ float biass[64];
    const u32 sb = smem_u32(smn);
    const int tid = threadIdx.x, lane = tid & 31, wid = tid >> 5;
    const int b = blockIdx.y;
    const int kl0 = blockIdx.x * 256;
    const int klw = wid * 64;          // warp kl offset within CTA

    if (tid < 64) biass[tid] = bias[tid];

    auto stage = [&](int ch, u32 sbuf){
        const __half* Hp = (ch == 0)
            ? g_x16 + (size_t)b*C_DIM*KLP
            : g_t16 + (size_t)((ch - 1)*B_DIM + b)*C_DIM*KLP;
        #pragma unroll
        for (int it = 0; it < 16; ++it) {         // A (H^T slab): 64 rows x 512B
            int e = tid + it*128;
            int i = e >> 5, q = e & 31;
            size_t go = (size_t)i*KLP + kl0 + q*8;
            cpa16(sbuf + CV_A + swz512((u32)(i*512 + q*16)), Hp + go);
        }
        #pragma unroll
        for (int it = 0; it < 4; ++it) {          // W: 64 rows x 128B
            int e = tid + it*128;
            int o = e >> 3, q = e & 7;
            size_t go = (size_t)o*320 + ch*64 + q*8;
            cpa16(sbuf + CV_W + swz128((u32)(o*128 + q*16)), g_wh + go);
        }
    };

    float acc[4][8][4];
    #pragma unroll
    for (int i = 0; i < 4; ++i)
        #pragma unroll
        for (int j = 0; j < 8; ++j)
            #pragma unroll
            for (int q = 0; q < 4; ++q) acc[i][j][q] = 0.f;

    stage(0, sb); CP_COMMIT();
    #pragma unroll 1
    for (int c = 0; c < 5; ++c) {
        if (c < 4) { stage(c + 1, sb + ((c + 1) & 1)*CV_SZ); CP_COMMIT(); CP_WAIT1(); }
        else       { CP_WAIT0(); }
        __syncthreads();
        const u32 buf = sb + (c & 1)*CV_SZ;
        #pragma unroll 1
        for (int kst = 0; kst < 4; ++kst) {
            u32 afr[4][4];
            #pragma unroll
            for (int mi = 0; mi < 4; ++mi)
                ldsm4t(afr[mi][0], afr[mi][1], afr[mi][2], afr[mi][3],
                       buf + CV_A + swz512((u32)((kst*16 + (lane & 7)
                            + ((lane >> 4) & 1)*8)*512
                            + (klw + mi*16)*2 + ((lane >> 3) & 1)*16)));
            u32 bfr[8][2];
            #pragma unroll
            for (int nj = 0; nj < 4; ++nj) {
                u32 r0, r1, r2, r3;
                ldsm4(r0, r1, r2, r3,
                      buf + CV_W + swz128((u32)((nj*16 + (lane & 15))*128
                                         + kst*32 + (lane >> 4)*16)));
                bfr[nj*2][0] = r0; bfr[nj*2][1] = r2;
                bfr[nj*2+1][0] = r1; bfr[nj*2+1][1] = r3;
            }
            #pragma unroll
            for (int mi = 0; mi < 4; ++mi)
                #pragma unroll
                for (int ntc = 0; ntc < 8; ++ntc)
                    mma_h(acc[mi][ntc], afr[mi], bfr[ntc]);
        }
        __syncthreads();
    }

    float* yb = y + (size_t)b*C_DIM*KL;
    #pragma unroll
    for (int mi = 0; mi < 4; ++mi) {
        int kl_r = kl0 + klw + mi*16 + (lane >> 2);
        #pragma unroll
        for (int ni = 0; ni < 8; ++ni) {
            int o = ni*8 + (lane & 3)*2;
            float b0 = biass[o], b1 = biass[o + 1];
            if (kl_r < KL) {
                yb[(size_t)o*KL + kl_r]         = acc[mi][ni][0] + b0;
                yb[(size_t)(o + 1)*KL + kl_r]   = acc[mi][ni][1] + b1;
            }
            if (kl_r + 8 < KL) {
                yb[(size_t)o*KL + kl_r + 8]       = acc[mi][ni][2] + b0;
                yb[(size_t)(o + 1)*KL + kl_r + 8] = acc[mi][ni][3] + b1;
            }
        }
    }
}

// =============================================================================
extern "C" void kernel_launch(void* const* d_in, const int* in_sizes, int n_in,
                              void* d_out, int out_size) {
    const float* x    = (const float*)d_in[0];
    const float* a0   = (const float*)d_in[1];
    const float* a1   = (const float*)d_in[2];
    const float* W    = (const float*)d_in[3];
    const float* bias = (const float*)d_in[4];
    float* y = (float*)d_out;

    cudaFuncSetAttribute(diffuse_mma, cudaFuncAttributeMaxDynamicSharedMemorySize, DF_SMEM);
    cudaFuncSetAttribute(conv_mma,    cudaFuncAttributeMaxDynamicSharedMemorySize, CV_SMEM);

    prep_x<<<32768, 256>>>(x);      // B*C*KLP/2 pairs
    prep_a<<<4096, 256>>>(a0, a1);  // 2*B*KP*KP/2 pairs
    prep_w<<<40, 256>>>(W);         // 64*320/2 pairs

    diffuse_mma<<<dim3(32, 2, 16), 256, DF_SMEM>>>(0);  // A0x, A1x (2-product)
    diffuse_mma<<<dim3(32, 2, 16), 256, DF_SMEM>>>(1);  // A0^2x, A1^2x (1-product)
    conv_mma   <<<dim3(52, 16),    128, CV_SMEM>>>(bias, y);
}